// round 6
// baseline (speedup 1.0000x reference)
#include <cuda_runtime.h>
#include <cuda_fp16.h>
#include <math.h>

#define DIM 32
#define NB 4096
#define KK 64
#define LL 2
#define N_ENTITY 500000
#define N_REL 64

// combo[i][d] = (half)E[i][d] in .x, (half)(E @ W_ih[:, :32]^T)[i][d] in .y
__device__ half2 g_combo[N_ENTITY * DIM];
__device__ float g_rproj[N_REL * DIM];
__device__ float g_rrr[N_REL];

__device__ __forceinline__ float tanh_approx(float x) {
    float y;
    asm("tanh.approx.f32 %0, %1;" : "=f"(y) : "f"(x));
    return y;
}

// ---------------------------------------------------------------------------
// Kernel A: warp-per-4-rows. Lane d holds W column d in registers (32 regs).
// Per row: 1 LDG (coalesced) + 32 SHFL + 32 FMA + 1 STG. No shared memory.
// ---------------------------------------------------------------------------
__global__ __launch_bounds__(256)
void project_entities(const float* __restrict__ E,
                      const float* __restrict__ W_ih) {
    int lane = threadIdx.x & 31;
    int warp = threadIdx.x >> 5;

    // w[e] = W_ih[lane*64 + e]  (Eproj[i][lane] = sum_e E[i][e]*W_ih[lane*64+e])
    float4 w4[8];
    const float4* wp = (const float4*)(W_ih + lane * 64);
    #pragma unroll
    for (int j = 0; j < 8; j++) w4[j] = wp[j];
    const float* w = (const float*)w4;

    int base = (blockIdx.x * 8 + warp) * 4;

    float x0 = 0.f, x1 = 0.f, x2 = 0.f, x3 = 0.f;
    bool v0 = base + 0 < N_ENTITY;
    bool v1 = base + 1 < N_ENTITY;
    bool v2 = base + 2 < N_ENTITY;
    bool v3 = base + 3 < N_ENTITY;
    if (v0) x0 = E[(base + 0) * 32 + lane];
    if (v1) x1 = E[(base + 1) * 32 + lane];
    if (v2) x2 = E[(base + 2) * 32 + lane];
    if (v3) x3 = E[(base + 3) * 32 + lane];

    float a0 = 0.f, a1 = 0.f, a2 = 0.f, a3 = 0.f;
    #pragma unroll
    for (int e = 0; e < 32; e++) {
        float we = w[e];
        a0 += __shfl_sync(0xffffffffu, x0, e) * we;
        a1 += __shfl_sync(0xffffffffu, x1, e) * we;
        a2 += __shfl_sync(0xffffffffu, x2, e) * we;
        a3 += __shfl_sync(0xffffffffu, x3, e) * we;
    }

    if (v0) g_combo[(base + 0) * 32 + lane] = __floats2half2_rn(x0, a0);
    if (v1) g_combo[(base + 1) * 32 + lane] = __floats2half2_rn(x1, a1);
    if (v2) g_combo[(base + 2) * 32 + lane] = __floats2half2_rn(x2, a2);
    if (v3) g_combo[(base + 3) * 32 + lane] = __floats2half2_rn(x3, a3);
}

// ---------------------------------------------------------------------------
// Kernel B: relation projections + dot(r,r). Tiny.
// ---------------------------------------------------------------------------
__global__ void project_relations(const float* __restrict__ R,
                                  const float* __restrict__ W_ih) {
    __shared__ float sW[32 * 32];
    int tid = threadIdx.x;
    for (int i = tid; i < 1024; i += blockDim.x) {
        int d = i >> 5, e = i & 31;
        sW[e * 32 + d] = W_ih[d * 64 + 32 + e];
    }
    __syncthreads();
    int lane = tid & 31;
    int warp = tid >> 5;
    for (int rel = warp; rel < N_REL; rel += 8) {
        float rv = R[rel * 32 + lane];
        float acc = 0.f;
        float rr = rv * rv;
        #pragma unroll
        for (int e = 0; e < 32; e++) {
            acc += __shfl_sync(0xffffffffu, rv, e) * sW[e * 32 + lane];
        }
        #pragma unroll
        for (int off = 16; off; off >>= 1)
            rr += __shfl_xor_sync(0xffffffffu, rr, off);
        g_rproj[rel * 32 + lane] = acc;
        if (lane == 0) g_rrr[rel] = rr;
    }
}

// ---------------------------------------------------------------------------
// Main kernel: WARP-PER-USER. Block = 8 warps = 8 users. Online softmax:
// no block barriers in the hot loop, no logit/h2 smem, h2 in registers.
// ---------------------------------------------------------------------------
__global__ __launch_bounds__(256)
void ripple_main(const int* __restrict__ users,
                 const int* __restrict__ items,
                 const int* __restrict__ hop0,
                 const int* __restrict__ heads,
                 const int* __restrict__ rels,
                 const int* __restrict__ tails,
                 const float* __restrict__ E,
                 const float* __restrict__ rec_user,
                 const float* __restrict__ rec_item,
                 const float* __restrict__ W_hh,
                 const float* __restrict__ b_ih,
                 const float* __restrict__ b_hh,
                 float* __restrict__ out) {
    __shared__ float s_rproj[N_REL * DIM];          // 8KB, shared by 8 users
    __shared__ float s_rrr[N_REL];
    __shared__ int s_hop0[8 * KK];                  // 2KB
    __shared__ int s_heads[LL * 8 * KK];            // 4KB
    __shared__ int s_rels[LL * 8 * KK];
    __shared__ int s_tails[LL * 8 * KK];
    __shared__ __align__(16) float sh1[8 * 8 * 32]; // 8KB: per-warp staging

    int tid = threadIdx.x;
    int lane = tid & 31;
    int warp = tid >> 5;
    int b = blockIdx.x * 8 + warp;                  // this warp's user

    // coalesced preloads (users are contiguous per block)
    if (tid < N_REL) s_rrr[tid] = g_rrr[tid];
    for (int i = tid; i < N_REL * DIM; i += 256) s_rproj[i] = g_rproj[i];
    for (int i = tid; i < 8 * KK; i += 256)
        s_hop0[i] = hop0[blockIdx.x * 8 * KK + i];
    for (int i = tid; i < LL * 8 * KK; i += 256) {
        int l = i >> 9, r = i & 511;
        int g = l * NB * KK + blockIdx.x * 8 * KK + r;
        s_heads[i] = heads[g];
        s_rels[i]  = rels[g];
        s_tails[i] = tails[g];
    }

    // per-lane register copy of W_hh row `lane`
    float4 whh[8];
    {
        const float4* wr = (const float4*)(W_hh + lane * 32);
        #pragma unroll
        for (int j = 0; j < 8; j++) whh[j] = wr[j];
    }
    float bz = b_ih[lane] + b_hh[lane];
    __syncthreads();

    float oseed = 0.f;

    // hop-0 seed sum (E half of combo), batched gathers
    #pragma unroll
    for (int g = 0; g < 2; g++) {
        half2 hv[32 / 8 * 4];  // 8... keep simple: 8 per group of 32? do 32 in 4 batches of 8
    }
    {
        const int* my0 = &s_hop0[warp * KK];
        #pragma unroll
        for (int g = 0; g < 8; g++) {
            half2 hv[8];
            #pragma unroll
            for (int kk = 0; kk < 8; kk++)
                hv[kk] = g_combo[my0[g * 8 + kk] * 32 + lane];
            #pragma unroll
            for (int kk = 0; kk < 8; kk++) oseed += __low2float(hv[kk]);
        }
    }

    float* myh1 = &sh1[warp * 256];
    const float4* h1_4 = (const float4*)myh1;

    for (int l = 0; l < LL; l++) {
        const int* mh = &s_heads[l * 512 + warp * KK];
        const int* mr = &s_rels [l * 512 + warp * KK];
        const int* mt = &s_tails[l * 512 + warp * KK];

        float m = -1e30f, ssum = 0.f, onum = 0.f;   // online softmax state

        #pragma unroll
        for (int g = 0; g < 8; g++) {
            // batch gathers for 8 triples
            half2 hv[8], tv[8];
            int ridx[8];
            #pragma unroll
            for (int kk = 0; kk < 8; kk++) {
                hv[kk] = g_combo[mh[g * 8 + kk] * 32 + lane];
                tv[kk] = g_combo[mt[g * 8 + kk] * 32 + lane];
                ridx[kk] = mr[g * 8 + kk];
            }

            float rp[8];
            #pragma unroll
            for (int kk = 0; kk < 8; kk++)
                rp[kk] = s_rproj[ridx[kk] * 32 + lane];

            // h1 -> smem staging
            #pragma unroll
            for (int kk = 0; kk < 8; kk++)
                myh1[kk * 32 + lane] =
                    tanh_approx(__high2float(hv[kk]) + rp[kk] + bz);

            // logits: butterfly reduce -> ALL lanes hold the value
            float lg[8];
            #pragma unroll
            for (int kk = 0; kk < 8; kk++)
                lg[kk] = __low2float(hv[kk]) * __low2float(tv[kk]);
            #pragma unroll
            for (int off = 16; off; off >>= 1) {
                #pragma unroll
                for (int kk = 0; kk < 8; kk++)
                    lg[kk] += __shfl_xor_sync(0xffffffffu, lg[kk], off);
            }
            #pragma unroll
            for (int kk = 0; kk < 8; kk++) lg[kk] += s_rrr[ridx[kk]];

            __syncwarp();  // h1 staging visible

            // joint matvec, j-outer (pipelined broadcast LDS.128)
            float acc[8];
            #pragma unroll
            for (int kk = 0; kk < 8; kk++)
                acc[kk] = __high2float(tv[kk]) + rp[kk] + bz;
            #pragma unroll
            for (int j = 0; j < 8; j++) {
                float4 wj = whh[j];
                #pragma unroll
                for (int kk = 0; kk < 8; kk++) {
                    float4 ha = h1_4[kk * 8 + j];
                    acc[kk] += ha.x * wj.x + ha.y * wj.y
                             + ha.z * wj.z + ha.w * wj.w;
                }
            }

            // online softmax update (all values warp-uniform except acc)
            float gm = lg[0];
            #pragma unroll
            for (int kk = 1; kk < 8; kk++) gm = fmaxf(gm, lg[kk]);
            float nm = fmaxf(m, gm);
            float scale = __expf(m - nm);
            ssum *= scale;
            onum *= scale;
            #pragma unroll
            for (int kk = 0; kk < 8; kk++) {
                float p = __expf(lg[kk] - nm);
                ssum += p;
                onum += p * tanh_approx(acc[kk]);
            }
            m = nm;
            __syncwarp();  // done reading sh1 before next group overwrites
        }

        oseed += onum / ssum;
    }

    // final score for this warp's user
    int u = users[b];
    int it = items[b];
    float uv = oseed + rec_user[u * 32 + lane];
    float iv = E[it * 32 + lane] + rec_item[it * 32 + lane];   // fp32 path
    float v = uv * iv;
    #pragma unroll
    for (int off = 16; off; off >>= 1)
        v += __shfl_xor_sync(0xffffffffu, v, off);
    if (lane == 0) out[b] = 1.f / (1.f + __expf(-v));
}

// ---------------------------------------------------------------------------
extern "C" void kernel_launch(void* const* d_in, const int* in_sizes, int n_in,
                              void* d_out, int out_size) {
    const int*   users      = (const int*)d_in[0];
    const int*   items      = (const int*)d_in[1];
    const int*   hop0_items = (const int*)d_in[2];
    const int*   heads      = (const int*)d_in[3];
    const int*   relations  = (const int*)d_in[4];
    const int*   tails      = (const int*)d_in[5];
    const float* entity_emb = (const float*)d_in[6];
    const float* rel_emb    = (const float*)d_in[7];
    const float* rec_user   = (const float*)d_in[8];
    const float* rec_item   = (const float*)d_in[9];
    const float* W_ih       = (const float*)d_in[10];
    const float* W_hh       = (const float*)d_in[11];
    const float* b_ih       = (const float*)d_in[12];
    const float* b_hh       = (const float*)d_in[13];
    float* out = (float*)d_out;

    // 8 warps/block, 4 rows/warp -> 32 rows per block
    project_entities<<<(N_ENTITY + 31) / 32, 256>>>(entity_emb, W_ih);
    project_relations<<<1, 256>>>(rel_emb, W_ih);
    ripple_main<<<NB / 8, 256>>>(users, items, hop0_items, heads, relations,
                                 tails, entity_emb, rec_user, rec_item,
                                 W_hh, b_ih, b_hh, out);
}

// round 7
// speedup vs baseline: 1.3015x; 1.3015x over previous
#include <cuda_runtime.h>
#include <cuda_fp16.h>
#include <math.h>

#define DIM 32
#define NB 4096
#define KK 64
#define LL 2
#define N_ENTITY 500000
#define N_REL 64

// combo[i][d] = (half)E[i][d] in .x, (half)(E @ W_ih[:, :32]^T)[i][d] in .y
__device__ half2 g_combo[N_ENTITY * DIM];
__device__ float g_rproj[N_REL * DIM];
__device__ float g_rrr[N_REL];

__device__ __forceinline__ float tanh_approx(float x) {
    float y;
    asm("tanh.approx.f32 %0, %1;" : "=f"(y) : "f"(x));
    return y;
}

// ---------------------------------------------------------------------------
// Kernel A: 4 rows per thread, outputs in 2 chunks of 16 (64 acc regs).
// Weights via warp-uniform LDS.128 broadcast; each LDS feeds 16 FMAs.
// Block covers 1024 consecutive rows (coalesced LDG: row = base + tid + q*256).
// ---------------------------------------------------------------------------
__global__ __launch_bounds__(256)
void project_entities(const float* __restrict__ E,
                      const float* __restrict__ W_ih) {
    __shared__ __align__(16) float sWT[32 * 32];  // sWT[e*32 + d] = W_ih[d*64 + e]
    int tid = threadIdx.x;
    for (int i = tid; i < 1024; i += 256) {
        int d = i >> 5, e = i & 31;
        sWT[e * 32 + d] = W_ih[d * 64 + e];
    }
    __syncthreads();

    int base = blockIdx.x * 1024 + tid;
    int row[4];
    bool ok[4];
    #pragma unroll
    for (int q = 0; q < 4; q++) {
        row[q] = base + q * 256;
        ok[q] = row[q] < N_ENTITY;
    }

    const float4* w4 = (const float4*)sWT;

    #pragma unroll
    for (int c = 0; c < 2; c++) {   // output chunk: d in [c*16, c*16+16)
        float4 acc[4][4];
        #pragma unroll
        for (int q = 0; q < 4; q++)
            #pragma unroll
            for (int j = 0; j < 4; j++)
                acc[q][j] = make_float4(0.f, 0.f, 0.f, 0.f);

        #pragma unroll
        for (int je = 0; je < 8; je++) {
            float4 x[4];
            #pragma unroll
            for (int q = 0; q < 4; q++)
                x[q] = ok[q] ? ((const float4*)(E + row[q] * 32))[je]
                             : make_float4(0.f, 0.f, 0.f, 0.f);
            #pragma unroll
            for (int ee = 0; ee < 4; ee++) {
                int e = je * 4 + ee;
                #pragma unroll
                for (int j = 0; j < 4; j++) {
                    float4 w = w4[e * 8 + c * 4 + j];  // uniform -> broadcast
                    #pragma unroll
                    for (int q = 0; q < 4; q++) {
                        float xe = (&x[q].x)[ee];
                        acc[q][j].x += xe * w.x;
                        acc[q][j].y += xe * w.y;
                        acc[q][j].z += xe * w.z;
                        acc[q][j].w += xe * w.w;
                    }
                }
            }
        }

        // pack + store this chunk: combo[row][d] = (half)E[row][d], (half)acc
        #pragma unroll
        for (int q = 0; q < 4; q++) {
            if (!ok[q]) continue;
            uint4* cp = (uint4*)(g_combo + row[q] * 32 + c * 16);
            #pragma unroll
            for (int j = 0; j < 4; j++) {
                float4 xd = ((const float4*)(E + row[q] * 32))[c * 4 + j]; // L1 hit
                half2 p0 = __floats2half2_rn(xd.x, acc[q][j].x);
                half2 p1 = __floats2half2_rn(xd.y, acc[q][j].y);
                half2 p2 = __floats2half2_rn(xd.z, acc[q][j].z);
                half2 p3 = __floats2half2_rn(xd.w, acc[q][j].w);
                uint4 o;
                o.x = *(unsigned int*)&p0; o.y = *(unsigned int*)&p1;
                o.z = *(unsigned int*)&p2; o.w = *(unsigned int*)&p3;
                cp[j] = o;
            }
        }
    }
}

// ---------------------------------------------------------------------------
// Kernel B: relation projections + dot(r,r). Tiny.
// ---------------------------------------------------------------------------
__global__ void project_relations(const float* __restrict__ R,
                                  const float* __restrict__ W_ih) {
    __shared__ float sW[32 * 32];
    int tid = threadIdx.x;
    for (int i = tid; i < 1024; i += blockDim.x) {
        int d = i >> 5, e = i & 31;
        sW[e * 32 + d] = W_ih[d * 64 + 32 + e];
    }
    __syncthreads();
    int lane = tid & 31;
    int warp = tid >> 5;
    for (int rel = warp; rel < N_REL; rel += 8) {
        float rv = R[rel * 32 + lane];
        float acc = 0.f;
        float rr = rv * rv;
        #pragma unroll
        for (int e = 0; e < 32; e++) {
            acc += __shfl_sync(0xffffffffu, rv, e) * sW[e * 32 + lane];
        }
        #pragma unroll
        for (int off = 16; off; off >>= 1)
            rr += __shfl_xor_sync(0xffffffffu, rr, off);
        g_rproj[rel * 32 + lane] = acc;
        if (lane == 0) g_rrr[rel] = rr;
    }
}

// ---------------------------------------------------------------------------
// Main kernel: WARP-PER-USER. Block = 8 warps = 8 users. Online softmax:
// no block barriers in the hot loop, no logit/h2 smem, h2 in registers.
// ---------------------------------------------------------------------------
__global__ __launch_bounds__(256)
void ripple_main(const int* __restrict__ users,
                 const int* __restrict__ items,
                 const int* __restrict__ hop0,
                 const int* __restrict__ heads,
                 const int* __restrict__ rels,
                 const int* __restrict__ tails,
                 const float* __restrict__ E,
                 const float* __restrict__ rec_user,
                 const float* __restrict__ rec_item,
                 const float* __restrict__ W_hh,
                 const float* __restrict__ b_ih,
                 const float* __restrict__ b_hh,
                 float* __restrict__ out) {
    __shared__ float s_rproj[N_REL * DIM];          // 8KB, shared by 8 users
    __shared__ float s_rrr[N_REL];
    __shared__ int s_hop0[8 * KK];                  // 2KB
    __shared__ int s_heads[LL * 8 * KK];            // 4KB
    __shared__ int s_rels[LL * 8 * KK];
    __shared__ int s_tails[LL * 8 * KK];
    __shared__ __align__(16) float sh1[8 * 8 * 32]; // 8KB: per-warp staging

    int tid = threadIdx.x;
    int lane = tid & 31;
    int warp = tid >> 5;
    int b = blockIdx.x * 8 + warp;                  // this warp's user

    // coalesced preloads (users are contiguous per block)
    if (tid < N_REL) s_rrr[tid] = g_rrr[tid];
    for (int i = tid; i < N_REL * DIM; i += 256) s_rproj[i] = g_rproj[i];
    for (int i = tid; i < 8 * KK; i += 256)
        s_hop0[i] = hop0[blockIdx.x * 8 * KK + i];
    for (int i = tid; i < LL * 8 * KK; i += 256) {
        int l = i >> 9, r = i & 511;
        int g = l * NB * KK + blockIdx.x * 8 * KK + r;
        s_heads[i] = heads[g];
        s_rels[i]  = rels[g];
        s_tails[i] = tails[g];
    }

    // per-lane register copy of W_hh row `lane`
    float4 whh[8];
    {
        const float4* wr = (const float4*)(W_hh + lane * 32);
        #pragma unroll
        for (int j = 0; j < 8; j++) whh[j] = wr[j];
    }
    float bz = b_ih[lane] + b_hh[lane];
    __syncthreads();

    float oseed = 0.f;

    // hop-0 seed sum (E half of combo), batched gathers
    {
        const int* my0 = &s_hop0[warp * KK];
        #pragma unroll
        for (int g = 0; g < 8; g++) {
            half2 hv[8];
            #pragma unroll
            for (int kk = 0; kk < 8; kk++)
                hv[kk] = g_combo[my0[g * 8 + kk] * 32 + lane];
            #pragma unroll
            for (int kk = 0; kk < 8; kk++) oseed += __low2float(hv[kk]);
        }
    }

    float* myh1 = &sh1[warp * 256];
    const float4* h1_4 = (const float4*)myh1;

    for (int l = 0; l < LL; l++) {
        const int* mh = &s_heads[l * 512 + warp * KK];
        const int* mr = &s_rels [l * 512 + warp * KK];
        const int* mt = &s_tails[l * 512 + warp * KK];

        float m = -1e30f, ssum = 0.f, onum = 0.f;   // online softmax state

        #pragma unroll
        for (int g = 0; g < 8; g++) {
            // batch gathers for 8 triples
            half2 hv[8], tv[8];
            int ridx[8];
            #pragma unroll
            for (int kk = 0; kk < 8; kk++) {
                hv[kk] = g_combo[mh[g * 8 + kk] * 32 + lane];
                tv[kk] = g_combo[mt[g * 8 + kk] * 32 + lane];
                ridx[kk] = mr[g * 8 + kk];
            }

            float rp[8];
            #pragma unroll
            for (int kk = 0; kk < 8; kk++)
                rp[kk] = s_rproj[ridx[kk] * 32 + lane];

            // h1 -> smem staging
            #pragma unroll
            for (int kk = 0; kk < 8; kk++)
                myh1[kk * 32 + lane] =
                    tanh_approx(__high2float(hv[kk]) + rp[kk] + bz);

            // logits: butterfly reduce -> ALL lanes hold the value
            float lg[8];
            #pragma unroll
            for (int kk = 0; kk < 8; kk++)
                lg[kk] = __low2float(hv[kk]) * __low2float(tv[kk]);
            #pragma unroll
            for (int off = 16; off; off >>= 1) {
                #pragma unroll
                for (int kk = 0; kk < 8; kk++)
                    lg[kk] += __shfl_xor_sync(0xffffffffu, lg[kk], off);
            }
            #pragma unroll
            for (int kk = 0; kk < 8; kk++) lg[kk] += s_rrr[ridx[kk]];

            __syncwarp();  // h1 staging visible

            // joint matvec, j-outer (pipelined broadcast LDS.128)
            float acc[8];
            #pragma unroll
            for (int kk = 0; kk < 8; kk++)
                acc[kk] = __high2float(tv[kk]) + rp[kk] + bz;
            #pragma unroll
            for (int j = 0; j < 8; j++) {
                float4 wj = whh[j];
                #pragma unroll
                for (int kk = 0; kk < 8; kk++) {
                    float4 ha = h1_4[kk * 8 + j];
                    acc[kk] += ha.x * wj.x + ha.y * wj.y
                             + ha.z * wj.z + ha.w * wj.w;
                }
            }

            // online softmax update
            float gm = lg[0];
            #pragma unroll
            for (int kk = 1; kk < 8; kk++) gm = fmaxf(gm, lg[kk]);
            float nm = fmaxf(m, gm);
            float scale = __expf(m - nm);
            ssum *= scale;
            onum *= scale;
            #pragma unroll
            for (int kk = 0; kk < 8; kk++) {
                float p = __expf(lg[kk] - nm);
                ssum += p;
                onum += p * tanh_approx(acc[kk]);
            }
            m = nm;
            __syncwarp();  // done reading sh1 before next group overwrites
        }

        oseed += onum / ssum;
    }

    // final score for this warp's user
    int u = users[b];
    int it = items[b];
    float uv = oseed + rec_user[u * 32 + lane];
    float iv = E[it * 32 + lane] + rec_item[it * 32 + lane];   // fp32 path
    float v = uv * iv;
    #pragma unroll
    for (int off = 16; off; off >>= 1)
        v += __shfl_xor_sync(0xffffffffu, v, off);
    if (lane == 0) out[b] = 1.f / (1.f + __expf(-v));
}

// ---------------------------------------------------------------------------
extern "C" void kernel_launch(void* const* d_in, const int* in_sizes, int n_in,
                              void* d_out, int out_size) {
    const int*   users      = (const int*)d_in[0];
    const int*   items      = (const int*)d_in[1];
    const int*   hop0_items = (const int*)d_in[2];
    const int*   heads      = (const int*)d_in[3];
    const int*   relations  = (const int*)d_in[4];
    const int*   tails      = (const int*)d_in[5];
    const float* entity_emb = (const float*)d_in[6];
    const float* rel_emb    = (const float*)d_in[7];
    const float* rec_user   = (const float*)d_in[8];
    const float* rec_item   = (const float*)d_in[9];
    const float* W_ih       = (const float*)d_in[10];
    const float* W_hh       = (const float*)d_in[11];
    const float* b_ih       = (const float*)d_in[12];
    const float* b_hh       = (const float*)d_in[13];
    float* out = (float*)d_out;

    project_entities<<<(N_ENTITY + 1023) / 1024, 256>>>(entity_emb, W_ih);
    project_relations<<<1, 256>>>(rel_emb, W_ih);
    ripple_main<<<NB / 8, 256>>>(users, items, hop0_items, heads, relations,
                                 tails, entity_emb, rec_user, rec_item,
                                 W_hh, b_ih, b_hh, out);
}

// round 8
// speedup vs baseline: 1.4115x; 1.0845x over previous
#include <cuda_runtime.h>
#include <cuda_fp16.h>
#include <math.h>

#define DIM 32
#define NB 4096
#define KK 64
#define LL 2
#define N_ENTITY 500000
#define N_REL 64
#define BU 4           // users per block in ripple_main

// combo[i][d] = (half)E[i][d] in .x, (half)(E @ W_ih[:, :32]^T)[i][d] in .y
__device__ half2 g_combo[N_ENTITY * DIM];
__device__ float g_rproj[N_REL * DIM];
__device__ float g_rrr[N_REL];

__device__ __forceinline__ float tanh_approx(float x) {
    float y;
    asm("tanh.approx.f32 %0, %1;" : "=f"(y) : "f"(x));
    return y;
}

// ---------------------------------------------------------------------------
// Kernel A: projection with smem-staged COALESCED global access.
// Pitch-36 padding makes both the fill (STS.128) and the per-row reads
// (LDS.128) bank-conflict free. x and acc live in registers during compute;
// output is re-staged through the same smem for coalesced STG.
// ---------------------------------------------------------------------------
__global__ __launch_bounds__(256)
void project_entities(const float* __restrict__ E,
                      const float* __restrict__ W_ih) {
    __shared__ __align__(16) float sWT[32 * 32];   // sWT[e*32+d] = W_ih[d*64+e]
    __shared__ __align__(16) float sX[256 * 36];   // 36KB padded tile

    int tid = threadIdx.x;
    for (int i = tid; i < 1024; i += 256) {
        int d = i >> 5, e = i & 31;
        sWT[e * 32 + d] = W_ih[d * 64 + e];
    }

    int base = blockIdx.x * 256;

    // coalesced fill: 2048 float4 loads across the block
    for (int i = tid; i < 2048; i += 256) {
        int row = i >> 3, j = i & 7;
        float4 v = (base + row < N_ENTITY)
                       ? ((const float4*)(E + (base + row) * 32))[j]
                       : make_float4(0.f, 0.f, 0.f, 0.f);
        ((float4*)(sX + row * 36))[j] = v;
    }
    __syncthreads();

    // per-thread row compute (x in regs, weights via broadcast LDS.128)
    float4 x[8];
    {
        const float4* xr = (const float4*)(sX + tid * 36);
        #pragma unroll
        for (int j = 0; j < 8; j++) x[j] = xr[j];
    }

    float4 acc[8];
    #pragma unroll
    for (int j = 0; j < 8; j++) acc[j] = make_float4(0.f, 0.f, 0.f, 0.f);

    const float4* w4 = (const float4*)sWT;
    #pragma unroll
    for (int je = 0; je < 8; je++) {
        float4 x4 = x[je];
        #pragma unroll
        for (int ee = 0; ee < 4; ee++) {
            float xe = (&x4.x)[ee];
            int e = je * 4 + ee;
            #pragma unroll
            for (int j = 0; j < 8; j++) {
                float4 w = w4[e * 8 + j];   // uniform address -> broadcast
                acc[j].x += xe * w.x;
                acc[j].y += xe * w.y;
                acc[j].z += xe * w.z;
                acc[j].w += xe * w.w;
            }
        }
    }
    __syncthreads();   // everyone done reading sX -> safe to reuse as staging

    // pack to half2 (E, proj) and stage into sX (same 144B pitch)
    {
        uint4* so = (uint4*)(sX + tid * 36);
        #pragma unroll
        for (int j = 0; j < 8; j++) {
            half2 p0 = __floats2half2_rn(x[j].x, acc[j].x);
            half2 p1 = __floats2half2_rn(x[j].y, acc[j].y);
            half2 p2 = __floats2half2_rn(x[j].z, acc[j].z);
            half2 p3 = __floats2half2_rn(x[j].w, acc[j].w);
            uint4 o;
            o.x = *(unsigned int*)&p0; o.y = *(unsigned int*)&p1;
            o.z = *(unsigned int*)&p2; o.w = *(unsigned int*)&p3;
            so[j] = o;
        }
    }
    __syncthreads();

    // coalesced store: 2048 uint4 across the block
    for (int i = tid; i < 2048; i += 256) {
        int row = i >> 3, j = i & 7;
        if (base + row < N_ENTITY) {
            uint4 v = ((const uint4*)(sX + row * 36))[j];
            ((uint4*)(g_combo + (base + row) * 32))[j] = v;
        }
    }
}

// ---------------------------------------------------------------------------
// Kernel B: relation projections + dot(r,r). Tiny.
// ---------------------------------------------------------------------------
__global__ void project_relations(const float* __restrict__ R,
                                  const float* __restrict__ W_ih) {
    __shared__ float sW[32 * 32];
    int tid = threadIdx.x;
    for (int i = tid; i < 1024; i += blockDim.x) {
        int d = i >> 5, e = i & 31;
        sW[e * 32 + d] = W_ih[d * 64 + 32 + e];
    }
    __syncthreads();
    int lane = tid & 31;
    int warp = tid >> 5;
    for (int rel = warp; rel < N_REL; rel += 8) {
        float rv = R[rel * 32 + lane];
        float acc = 0.f;
        float rr = rv * rv;
        #pragma unroll
        for (int e = 0; e < 32; e++) {
            acc += __shfl_sync(0xffffffffu, rv, e) * sW[e * 32 + lane];
        }
        #pragma unroll
        for (int off = 16; off; off >>= 1)
            rr += __shfl_xor_sync(0xffffffffu, rr, off);
        g_rproj[rel * 32 + lane] = acc;
        if (lane == 0) g_rrr[rel] = rr;
    }
}

// ---------------------------------------------------------------------------
// Main kernel: WARP-PER-USER, 4 users/block (128 thr). Online softmax, no
// block barriers in the hot loop. Gathers double-buffered across groups.
// ---------------------------------------------------------------------------
__global__ __launch_bounds__(128)
void ripple_main(const int* __restrict__ users,
                 const int* __restrict__ items,
                 const int* __restrict__ hop0,
                 const int* __restrict__ heads,
                 const int* __restrict__ rels,
                 const int* __restrict__ tails,
                 const float* __restrict__ E,
                 const float* __restrict__ rec_user,
                 const float* __restrict__ rec_item,
                 const float* __restrict__ W_hh,
                 const float* __restrict__ b_ih,
                 const float* __restrict__ b_hh,
                 float* __restrict__ out) {
    __shared__ float s_rproj[N_REL * DIM];            // 8KB, shared by 4 users
    __shared__ float s_rrr[N_REL];
    __shared__ int s_hop0[BU * KK];                   // 1KB
    __shared__ int s_heads[LL * BU * KK];             // 2KB
    __shared__ int s_rels[LL * BU * KK];
    __shared__ int s_tails[LL * BU * KK];
    __shared__ __align__(16) float sh1[BU * 8 * 32];  // 4KB per-warp staging

    int tid = threadIdx.x;
    int lane = tid & 31;
    int warp = tid >> 5;
    int b = blockIdx.x * BU + warp;

    // coalesced preloads
    if (tid < N_REL) s_rrr[tid] = g_rrr[tid];
    for (int i = tid; i < N_REL * DIM; i += 128) s_rproj[i] = g_rproj[i];
    for (int i = tid; i < BU * KK; i += 128)
        s_hop0[i] = hop0[blockIdx.x * BU * KK + i];
    for (int i = tid; i < LL * BU * KK; i += 128) {
        int l = i >> 8, r = i & 255;
        int g = l * NB * KK + blockIdx.x * BU * KK + r;
        s_heads[i] = heads[g];
        s_rels[i]  = rels[g];
        s_tails[i] = tails[g];
    }

    float4 whh[8];
    {
        const float4* wr = (const float4*)(W_hh + lane * 32);
        #pragma unroll
        for (int j = 0; j < 8; j++) whh[j] = wr[j];
    }
    float bz = b_ih[lane] + b_hh[lane];
    __syncthreads();

    float oseed = 0.f;

    // hop-0 seed sum
    {
        const int* my0 = &s_hop0[warp * KK];
        #pragma unroll
        for (int g = 0; g < 8; g++) {
            half2 hv[8];
            #pragma unroll
            for (int kk = 0; kk < 8; kk++)
                hv[kk] = g_combo[my0[g * 8 + kk] * 32 + lane];
            #pragma unroll
            for (int kk = 0; kk < 8; kk++) oseed += __low2float(hv[kk]);
        }
    }

    float* myh1 = &sh1[warp * 256];
    const float4* h1_4 = (const float4*)myh1;

    for (int l = 0; l < LL; l++) {
        const int* mh = &s_heads[l * (BU * KK) + warp * KK];
        const int* mr = &s_rels [l * (BU * KK) + warp * KK];
        const int* mt = &s_tails[l * (BU * KK) + warp * KK];

        float m = -1e30f, ssum = 0.f, onum = 0.f;

        // prologue: gathers for group 0
        half2 hv[8], tv[8];
        int ridx[8];
        #pragma unroll
        for (int kk = 0; kk < 8; kk++) {
            hv[kk] = g_combo[mh[kk] * 32 + lane];
            tv[kk] = g_combo[mt[kk] * 32 + lane];
            ridx[kk] = mr[kk];
        }

        #pragma unroll
        for (int g = 0; g < 8; g++) {
            // prefetch group g+1 gathers (overlap with compute below)
            half2 hvn[8], tvn[8];
            int ridxn[8];
            if (g < 7) {
                #pragma unroll
                for (int kk = 0; kk < 8; kk++) {
                    hvn[kk] = g_combo[mh[(g + 1) * 8 + kk] * 32 + lane];
                    tvn[kk] = g_combo[mt[(g + 1) * 8 + kk] * 32 + lane];
                    ridxn[kk] = mr[(g + 1) * 8 + kk];
                }
            }

            float rp[8];
            #pragma unroll
            for (int kk = 0; kk < 8; kk++)
                rp[kk] = s_rproj[ridx[kk] * 32 + lane];

            // h1 -> smem staging
            #pragma unroll
            for (int kk = 0; kk < 8; kk++)
                myh1[kk * 32 + lane] =
                    tanh_approx(__high2float(hv[kk]) + rp[kk] + bz);

            // logits: butterfly -> all lanes hold value
            float lg[8];
            #pragma unroll
            for (int kk = 0; kk < 8; kk++)
                lg[kk] = __low2float(hv[kk]) * __low2float(tv[kk]);
            #pragma unroll
            for (int off = 16; off; off >>= 1) {
                #pragma unroll
                for (int kk = 0; kk < 8; kk++)
                    lg[kk] += __shfl_xor_sync(0xffffffffu, lg[kk], off);
            }
            #pragma unroll
            for (int kk = 0; kk < 8; kk++) lg[kk] += s_rrr[ridx[kk]];

            __syncwarp();  // h1 staging visible

            // joint matvec, j-outer
            float acc[8];
            #pragma unroll
            for (int kk = 0; kk < 8; kk++)
                acc[kk] = __high2float(tv[kk]) + rp[kk] + bz;
            #pragma unroll
            for (int j = 0; j < 8; j++) {
                float4 wj = whh[j];
                #pragma unroll
                for (int kk = 0; kk < 8; kk++) {
                    float4 ha = h1_4[kk * 8 + j];
                    acc[kk] += ha.x * wj.x + ha.y * wj.y
                             + ha.z * wj.z + ha.w * wj.w;
                }
            }

            // online softmax update
            float gm = lg[0];
            #pragma unroll
            for (int kk = 1; kk < 8; kk++) gm = fmaxf(gm, lg[kk]);
            float nm = fmaxf(m, gm);
            float scale = __expf(m - nm);
            ssum *= scale;
            onum *= scale;
            #pragma unroll
            for (int kk = 0; kk < 8; kk++) {
                float p = __expf(lg[kk] - nm);
                ssum += p;
                onum += p * tanh_approx(acc[kk]);
            }
            m = nm;
            __syncwarp();  // done reading sh1 before next group overwrites

            if (g < 7) {
                #pragma unroll
                for (int kk = 0; kk < 8; kk++) {
                    hv[kk] = hvn[kk];
                    tv[kk] = tvn[kk];
                    ridx[kk] = ridxn[kk];
                }
            }
        }

        oseed += onum / ssum;
    }

    // final score
    int u = users[b];
    int it = items[b];
    float uv = oseed + rec_user[u * 32 + lane];
    float iv = E[it * 32 + lane] + rec_item[it * 32 + lane];
    float v = uv * iv;
    #pragma unroll
    for (int off = 16; off; off >>= 1)
        v += __shfl_xor_sync(0xffffffffu, v, off);
    if (lane == 0) out[b] = 1.f / (1.f + __expf(-v));
}

// ---------------------------------------------------------------------------
extern "C" void kernel_launch(void* const* d_in, const int* in_sizes, int n_in,
                              void* d_out, int out_size) {
    const int*   users      = (const int*)d_in[0];
    const int*   items      = (const int*)d_in[1];
    const int*   hop0_items = (const int*)d_in[2];
    const int*   heads      = (const int*)d_in[3];
    const int*   relations  = (const int*)d_in[4];
    const int*   tails      = (const int*)d_in[5];
    const float* entity_emb = (const float*)d_in[6];
    const float* rel_emb    = (const float*)d_in[7];
    const float* rec_user   = (const float*)d_in[8];
    const float* rec_item   = (const float*)d_in[9];
    const float* W_ih       = (const float*)d_in[10];
    const float* W_hh       = (const float*)d_in[11];
    const float* b_ih       = (const float*)d_in[12];
    const float* b_hh       = (const float*)d_in[13];
    float* out = (float*)d_out;

    project_entities<<<(N_ENTITY + 255) / 256, 256>>>(entity_emb, W_ih);
    project_relations<<<1, 256>>>(rel_emb, W_ih);
    ripple_main<<<NB / BU, 128>>>(users, items, hop0_items, heads, relations,
                                  tails, entity_emb, rec_user, rec_item,
                                  W_hh, b_ih, b_hh, out);
}